// round 7
// baseline (speedup 1.0000x reference)
#include <cuda_runtime.h>

#define BB   32
#define TT   4096
#define DD   512
#define GG   8
#define OO   512
#define CHUNK 128
#define NCHUNK (TT/CHUNK)   // 32

// Scratch (__device__ globals; no allocations allowed)
__device__ float d_sums[BB*GG*DD];
__device__ int   d_counts[BB*GG];
__device__ int   d_st[TT];      // token ids, group-sorted (shared across b)
__device__ int   d_sg[TT];      // group id per sorted slot

// ---------------------------------------------------------------- zero
// grid 128 x 256: one float4 per thread over d_sums; CTA 0 zeros counts.
__global__ void __launch_bounds__(256) k_zero() {
    int i = blockIdx.x * 256 + threadIdx.x;
    ((float4*)d_sums)[i] = make_float4(0.f,0.f,0.f,0.f);
    if (blockIdx.x == 0 && threadIdx.x < BB*GG) d_counts[threadIdx.x] = 0;
}

// ---------------------------------------------------------------- sort
// 1 CTA, 8 warps. Warp g scans all TT token types (16 KB, L1-resident after
// first touch) and ballot-compacts its group's token ids. No atomics, no
// scan chains; output ascending by token id within each group.
__global__ void __launch_bounds__(256) k_sort(const int* __restrict__ tt) {
    __shared__ int s_cnt[GG];
    int tid  = threadIdx.x;
    int lane = tid & 31;
    int w    = tid >> 5;          // warp == group

    // pass 1: count my group (unroll 4 for MLP)
    int c = 0;
    #pragma unroll 4
    for (int t0 = 0; t0 < TT; t0 += 32)
        c += (tt[t0 + lane] == w);
    #pragma unroll
    for (int off = 16; off > 0; off >>= 1)
        c += __shfl_down_sync(0xffffffffu, c, off);
    if (lane == 0) s_cnt[w] = c;
    __syncthreads();

    // exclusive base for my group (tiny, every thread computes)
    int base = 0;
    #pragma unroll
    for (int g = 0; g < GG; g++) base += (g < w) ? s_cnt[g] : 0;

    // pass 2: ballot compaction
    int pos = base;
    for (int t0 = 0; t0 < TT; t0 += 32) {
        int g = tt[t0 + lane];
        unsigned m = __ballot_sync(0xffffffffu, g == w);
        if (g == w) {
            int r = __popc(m & ((1u << lane) - 1u));
            d_st[pos + r] = t0 + lane;
            d_sg[pos + r] = w;
        }
        pos += __popc(m);
    }
}

// ------------------------------------------------------------- masked sums
// grid (NCHUNK, BB), 256 threads. lane = tid&127 owns one float4 of D=512,
// half = tid>>7 strides tokens by 2 -> 64 tokens per thread, 8 macro-steps.
// Branch-free inner loop: invalid steps load a dummy L1-hot row (s_tok[0])
// and accumulate via fmaf(mask, v, acc) -> unbroken 8-wide LDG batches.
// Group-sorted order -> accumulator flushes via atomicAdd only at group
// boundaries (~1-2 per chunk).
__device__ __forceinline__ void flush_acc(int b, int g, int lane, float4 a) {
    float* dst = &d_sums[((size_t)b*GG + g)*DD + lane*4];
    atomicAdd(dst+0, a.x); atomicAdd(dst+1, a.y);
    atomicAdd(dst+2, a.z); atomicAdd(dst+3, a.w);
}

__global__ void __launch_bounds__(256) k_main(const float* __restrict__ batch,
                                              const int* __restrict__ pad) {
    __shared__ int s_tok[CHUNK];
    __shared__ int s_grp[CHUNK];
    __shared__ int s_val[CHUNK];

    int b   = blockIdx.y;
    int c0  = blockIdx.x * CHUNK;
    int tid = threadIdx.x;

    if (tid < CHUNK) {
        int t = d_st[c0 + tid];
        s_tok[tid] = t;
        s_grp[tid] = d_sg[c0 + tid];
        s_val[tid] = pad[(size_t)b*TT + t] ? 0 : 1;   // bool -> int32 transport
    }
    __syncthreads();

    // per-(b,g) valid counts: 64 threads, 16 smem reads each
    if (tid < 64) {
        int g = tid >> 3, j = tid & 7;
        int c = 0;
        #pragma unroll
        for (int k = 0; k < 16; k++) {
            int i = j*16 + k;
            c += (s_grp[i] == g) & s_val[i];
        }
        if (c) atomicAdd(&d_counts[b*GG + g], c);
    }

    int lane = tid & 127;
    int half = tid >> 7;
    const float4* bb = (const float4*)(batch + (size_t)b * TT * DD);
    int tsafe = s_tok[0];          // dummy row, L1-hot after first touch

    float4 acc = make_float4(0.f,0.f,0.f,0.f);
    int curg = s_grp[0];

    #define PLOAD(V, M, J)                                                  \
        int vv_##V = s_val[i + 2*(J)];                                      \
        int ti_##V = vv_##V ? s_tok[i + 2*(J)] : tsafe;                     \
        float M = (float)vv_##V;                                            \
        float4 V = __ldcs(&bb[(size_t)ti_##V * (DD/4) + lane]);

    #define ACCSTEP(J, V, M)                                                \
        { int g_ = s_grp[i + 2*(J)];                                        \
          if (g_ != curg) {                        /* warp-uniform, rare */ \
              flush_acc(b, curg, lane, acc);                                \
              acc = make_float4(0.f,0.f,0.f,0.f); curg = g_; }              \
          acc.x = fmaf(M, (V).x, acc.x); acc.y = fmaf(M, (V).y, acc.y);     \
          acc.z = fmaf(M, (V).z, acc.z); acc.w = fmaf(M, (V).w, acc.w); }

    #pragma unroll
    for (int s = 0; s < 8; s++) {
        int i = half + s*16;
        PLOAD(v0, m0, 0) PLOAD(v1, m1, 1) PLOAD(v2, m2, 2) PLOAD(v3, m3, 3)
        PLOAD(v4, m4, 4) PLOAD(v5, m5, 5) PLOAD(v6, m6, 6) PLOAD(v7, m7, 7)
        ACCSTEP(0, v0, m0); ACCSTEP(1, v1, m1);
        ACCSTEP(2, v2, m2); ACCSTEP(3, v3, m3);
        ACCSTEP(4, v4, m4); ACCSTEP(5, v5, m5);
        ACCSTEP(6, v6, m6); ACCSTEP(7, v7, m7);
    }
    flush_acc(b, curg, lane, acc);
    #undef PLOAD
    #undef ACCSTEP
}

// ------------------------------------------------------ means -> GEMM + bias
// grid (G, OO/128, BB/8), 256 threads. Tile: 8 b-rows x 128 outputs.
// Thread = 1 b-row x 4 outputs; mean reads are warp-broadcast.
#define GBH  8
#define GOCH 128
#define GDT  16

__global__ void __launch_bounds__(256) k_gemm(const float* __restrict__ W,
                                              const float* __restrict__ bias,
                                              float* __restrict__ out) {
    __shared__ float s_mean[GBH * DD];      // 16 KB
    __shared__ float s_w[GDT * GOCH];       //  8 KB

    int g   = blockIdx.x;
    int o0  = blockIdx.y * GOCH;
    int b0  = blockIdx.z * GBH;
    int tid = threadIdx.x;

    for (int idx = tid; idx < GBH*DD; idx += 256) {
        int bl = idx >> 9;
        int d  = idx & (DD-1);
        int bg = (b0 + bl)*GG + g;
        int c  = d_counts[bg];
        float s = d_sums[(size_t)bg*DD + d];
        s_mean[bl*DD + d] = (c > 0) ? s / (float)c : 0.0f;
    }

    int oq   = tid & 31;
    int brow = tid >> 5;
    float a0=0.f, a1=0.f, a2=0.f, a3=0.f;

    for (int d0 = 0; d0 < DD; d0 += GDT) {
        __syncthreads();
        #pragma unroll
        for (int k = 0; k < 2; k++) {
            int idx = tid + k*256;
            int dd  = idx >> 5;
            int o4  = idx & 31;
            ((float4*)s_w)[idx] =
                *((const float4*)(W + ((size_t)(g*DD + d0 + dd))*OO + o0) + o4);
        }
        __syncthreads();

        #pragma unroll
        for (int dd = 0; dd < GDT; dd++) {
            float4 w = ((const float4*)s_w)[dd*32 + oq];
            float  m = s_mean[brow*DD + d0 + dd];
            a0 += m*w.x; a1 += m*w.y; a2 += m*w.z; a3 += m*w.w;
        }
    }

    int o = o0 + oq*4;
    float4 bv = *(const float4*)(bias + (size_t)g*OO + o);
    float4 r = make_float4(a0+bv.x, a1+bv.y, a2+bv.z, a3+bv.w);
    *(float4*)(out + ((size_t)((b0 + brow)*GG + g))*OO + o) = r;
}

// ---------------------------------------------------------------- launcher
// metadata order: batch(f32), W(f32), b_bias(f32), token_types(i32),
//                 key_padding_mask(bool -> int32)
extern "C" void kernel_launch(void* const* d_in, const int* in_sizes, int n_in,
                              void* d_out, int out_size) {
    const float* batch = (const float*)d_in[0];
    const float* W     = (const float*)d_in[1];
    const float* bias  = (const float*)d_in[2];
    const int*   tt    = (const int*)d_in[3];
    const int*   pad   = (const int*)d_in[4];
    float* out = (float*)d_out;

    k_zero<<<BB*GG*DD/(256*4), 256>>>();
    k_sort<<<1, 256>>>(tt);

    dim3 gmain(NCHUNK, BB);
    k_main<<<gmain, 256>>>(batch, pad);

    dim3 ggemm(GG, OO/GOCH, BB/GBH);
    k_gemm<<<ggemm, 256>>>(W, bias, out);
}

// round 8
// speedup vs baseline: 1.0963x; 1.0963x over previous
#include <cuda_runtime.h>

#define BB   32
#define TT   4096
#define DD   512
#define GG   8
#define OO   512
#define CHUNK 128
#define NCHUNK (TT/CHUNK)   // 32

// Scratch (__device__ globals; no allocations allowed)
__device__ float d_sums[BB*GG*DD];
__device__ int   d_counts[BB*GG];
__device__ int   d_st[TT];      // token ids, group-sorted (shared across b)
__device__ int   d_sg[TT];      // group id per sorted slot

// ---------------------------------------------------------------- zero
__global__ void __launch_bounds__(256) k_zero() {
    int i = blockIdx.x * 256 + threadIdx.x;
    ((float4*)d_sums)[i] = make_float4(0.f,0.f,0.f,0.f);
    if (blockIdx.x == 0 && threadIdx.x < BB*GG) d_counts[threadIdx.x] = 0;
}

// ---------------------------------------------------------------- sort
// 1 CTA, 8 warps. Warp g scans all TT token types (16 KB, L1-resident after
// first pass) and ballot-compacts its group's token ids. No atomics.
__global__ void __launch_bounds__(256) k_sort(const int* __restrict__ tt) {
    __shared__ int s_cnt[GG];
    int tid  = threadIdx.x;
    int lane = tid & 31;
    int w    = tid >> 5;          // warp == group

    int c = 0;
    #pragma unroll 4
    for (int t0 = 0; t0 < TT; t0 += 32)
        c += (tt[t0 + lane] == w);
    #pragma unroll
    for (int off = 16; off > 0; off >>= 1)
        c += __shfl_down_sync(0xffffffffu, c, off);
    if (lane == 0) s_cnt[w] = c;
    __syncthreads();

    int base = 0;
    #pragma unroll
    for (int g = 0; g < GG; g++) base += (g < w) ? s_cnt[g] : 0;

    int pos = base;
    for (int t0 = 0; t0 < TT; t0 += 32) {
        int g = tt[t0 + lane];
        unsigned m = __ballot_sync(0xffffffffu, g == w);
        if (g == w) {
            int r = __popc(m & ((1u << lane) - 1u));
            d_st[pos + r] = t0 + lane;
            d_sg[pos + r] = w;
        }
        pos += __popc(m);
    }
}

// ------------------------------------------------------------- masked sums
// grid (NCHUNK, BB), 256 threads (R4-measured-best variant). lane = tid&127
// owns one float4 of D=512, half = tid>>7 strides tokens by 2. Warp-uniform
// predicated loads (@!P issues no transaction), 8-wide front-batched.
// Accumulator flushes via atomicAdd only at group boundaries.
__device__ __forceinline__ void flush_acc(int b, int g, int lane, float4 a) {
    float* dst = &d_sums[((size_t)b*GG + g)*DD + lane*4];
    atomicAdd(dst+0, a.x); atomicAdd(dst+1, a.y);
    atomicAdd(dst+2, a.z); atomicAdd(dst+3, a.w);
}

__global__ void __launch_bounds__(256) k_main(const float* __restrict__ batch,
                                              const int* __restrict__ pad) {
    __shared__ int s_tok[CHUNK];
    __shared__ int s_grp[CHUNK];
    __shared__ int s_val[CHUNK];

    int b   = blockIdx.y;
    int c0  = blockIdx.x * CHUNK;
    int tid = threadIdx.x;

    if (tid < CHUNK) {
        int t = d_st[c0 + tid];
        s_tok[tid] = t;
        s_grp[tid] = d_sg[c0 + tid];
        s_val[tid] = pad[(size_t)b*TT + t] ? 0 : 1;   // bool -> int32 transport
    }
    __syncthreads();

    // per-(b,g) valid counts: 64 threads, 16 smem reads each
    if (tid < 64) {
        int g = tid >> 3, j = tid & 7;
        int c = 0;
        #pragma unroll
        for (int k = 0; k < 16; k++) {
            int i = j*16 + k;
            c += (s_grp[i] == g) & s_val[i];
        }
        if (c) atomicAdd(&d_counts[b*GG + g], c);
    }

    int lane = tid & 127;
    int half = tid >> 7;
    const float4* bb = (const float4*)(batch + (size_t)b * TT * DD);

    float4 acc = make_float4(0.f,0.f,0.f,0.f);
    int curg = s_grp[0];

    #define PLOAD(V, J)                                                     \
        float4 V = make_float4(0.f,0.f,0.f,0.f);                            \
        if (s_val[i + 2*(J)])                                               \
            V = __ldcs(&bb[(size_t)s_tok[i + 2*(J)] * (DD/4) + lane]);

    #define ACCSTEP(J, V)                                                   \
        { int g_ = s_grp[i + 2*(J)];                                        \
          if (g_ != curg) {                                                 \
              flush_acc(b, curg, lane, acc);                                \
              acc = make_float4(0.f,0.f,0.f,0.f); curg = g_; }              \
          acc.x += (V).x; acc.y += (V).y; acc.z += (V).z; acc.w += (V).w; }

    #pragma unroll
    for (int s = 0; s < 8; s++) {
        int i = half + s*16;
        PLOAD(v0, 0) PLOAD(v1, 1) PLOAD(v2, 2) PLOAD(v3, 3)
        PLOAD(v4, 4) PLOAD(v5, 5) PLOAD(v6, 6) PLOAD(v7, 7)
        ACCSTEP(0, v0); ACCSTEP(1, v1); ACCSTEP(2, v2); ACCSTEP(3, v3);
        ACCSTEP(4, v4); ACCSTEP(5, v5); ACCSTEP(6, v6); ACCSTEP(7, v7);
    }
    flush_acc(b, curg, lane, acc);
    #undef PLOAD
    #undef ACCSTEP
}

// ------------------------------------------------------ means -> GEMM + bias
// grid (8 g, 16 o-blocks of 32, 2 b-slabs of 16) = 256 CTAs, 256 threads.
// Whole W o-slice (512x32 = 64KB) + 16 b-rows of means (32KB) loaded into
// dynamic smem in one front-batched burst, ONE sync, then a sync-free
// 512-step dot loop. Thread = 2 b-rows x 1 output.
#define GBH2 16
#define GO2  32
#define GEMM_SMEM ((DD*GO2 + GBH2*DD) * 4)   // 98304 B

__global__ void __launch_bounds__(256) k_gemm(const float* __restrict__ W,
                                              const float* __restrict__ bias,
                                              float* __restrict__ out) {
    extern __shared__ float sm[];
    float* s_w    = sm;              // [512][32]
    float* s_mean = sm + DD*GO2;     // [16][512]

    int g   = blockIdx.x;
    int o0  = blockIdx.y * GO2;
    int b0  = blockIdx.z * GBH2;
    int tid = threadIdx.x;

    // W block: 512 rows x 32 cols -> 4096 float4, 16 per thread, coalesced
    const float4* wg = (const float4*)(W + (size_t)g*DD*OO);
    #pragma unroll
    for (int i = 0; i < 16; i++) {
        int idx = tid + i*256;         // 0..4095
        int k   = idx >> 3;
        int c4  = idx & 7;
        ((float4*)s_w)[idx] = wg[(size_t)k*(OO/4) + (o0>>2) + c4];
        // note: s_w float4-index idx == k*8 + c4, matching [k][32] layout
    }
    // means: 16 x 512 floats, divide-by-count on load
    for (int idx = tid; idx < GBH2*DD; idx += 256) {
        int bl = idx >> 9;
        int d  = idx & (DD-1);
        int bg = (b0 + bl)*GG + g;
        int c  = d_counts[bg];
        float s = d_sums[(size_t)bg*DD + d];
        s_mean[bl*DD + d] = (c > 0) ? s / (float)c : 0.0f;
    }
    __syncthreads();

    int o  = tid & 31;          // warp = 32 consecutive o -> conflict-free LDS
    int bq = tid >> 5;          // 8 pairs -> 16 b-rows
    const float* m0 = s_mean + (bq*2 + 0)*DD;
    const float* m1 = s_mean + (bq*2 + 1)*DD;
    float a0 = 0.f, a1 = 0.f;

    #pragma unroll 8
    for (int k = 0; k < DD; k++) {
        float w = s_w[k*GO2 + o];
        a0 = fmaf(m0[k], w, a0);
        a1 = fmaf(m1[k], w, a1);
    }

    float bv = bias[(size_t)g*OO + o0 + o];
    int ba = b0 + bq*2, bc = ba + 1;
    out[((size_t)ba*GG + g)*OO + o0 + o] = a0 + bv;
    out[((size_t)bc*GG + g)*OO + o0 + o] = a1 + bv;
}

// ---------------------------------------------------------------- launcher
// metadata order: batch(f32), W(f32), b_bias(f32), token_types(i32),
//                 key_padding_mask(bool -> int32)
extern "C" void kernel_launch(void* const* d_in, const int* in_sizes, int n_in,
                              void* d_out, int out_size) {
    const float* batch = (const float*)d_in[0];
    const float* W     = (const float*)d_in[1];
    const float* bias  = (const float*)d_in[2];
    const int*   tt    = (const int*)d_in[3];
    const int*   pad   = (const int*)d_in[4];
    float* out = (float*)d_out;

    static int smem_set = 0;
    if (!smem_set) {
        cudaFuncSetAttribute(k_gemm, cudaFuncAttributeMaxDynamicSharedMemorySize,
                             GEMM_SMEM);
        smem_set = 1;
    }

    k_zero<<<BB*GG*DD/(256*4), 256>>>();
    k_sort<<<1, 256>>>(tt);

    dim3 gmain(NCHUNK, BB);
    k_main<<<gmain, 256>>>(batch, pad);

    dim3 ggemm(GG, OO/GO2, BB/GBH2);
    k_gemm<<<ggemm, 256, GEMM_SMEM>>>(W, bias, out);
}

// round 9
// speedup vs baseline: 1.1157x; 1.0178x over previous
#include <cuda_runtime.h>

#define BB   32
#define TT   4096
#define DD   512
#define GG   8
#define OO   512
#define CHUNK 128
#define NCHUNK (TT/CHUNK)   // 32

// Scratch (__device__ globals; no allocations allowed)
__device__ float d_sums[BB*GG*DD];
__device__ int   d_counts[BB*GG];
__device__ int   d_st[TT];      // token ids, group-sorted (shared across b)
__device__ int   d_sg[TT];      // group id per sorted slot

// ---------------------------------------------------------------- zero
__global__ void __launch_bounds__(256) k_zero() {
    int i = blockIdx.x * 256 + threadIdx.x;
    ((float4*)d_sums)[i] = make_float4(0.f,0.f,0.f,0.f);
    if (blockIdx.x == 0 && threadIdx.x < BB*GG) d_counts[threadIdx.x] = 0;
}

// ---------------------------------------------------------------- sort
// 1 CTA, 8 warps. Warp g scans all TT token types (16 KB, L1-resident after
// first pass) and ballot-compacts its group's token ids. No atomics.
__global__ void __launch_bounds__(256) k_sort(const int* __restrict__ tt) {
    __shared__ int s_cnt[GG];
    int tid  = threadIdx.x;
    int lane = tid & 31;
    int w    = tid >> 5;          // warp == group

    int c = 0;
    #pragma unroll 4
    for (int t0 = 0; t0 < TT; t0 += 32)
        c += (tt[t0 + lane] == w);
    #pragma unroll
    for (int off = 16; off > 0; off >>= 1)
        c += __shfl_down_sync(0xffffffffu, c, off);
    if (lane == 0) s_cnt[w] = c;
    __syncthreads();

    int base = 0;
    #pragma unroll
    for (int g = 0; g < GG; g++) base += (g < w) ? s_cnt[g] : 0;

    int pos = base;
    for (int t0 = 0; t0 < TT; t0 += 32) {
        int g = tt[t0 + lane];
        unsigned m = __ballot_sync(0xffffffffu, g == w);
        if (g == w) {
            int r = __popc(m & ((1u << lane) - 1u));
            d_st[pos + r] = t0 + lane;
            d_sg[pos + r] = w;
        }
        pos += __popc(m);
    }
}

// ------------------------------------------------------------- masked sums
// grid (NCHUNK, BB), 256 threads (R4-measured-best variant). lane = tid&127
// owns one float4 of D=512, half = tid>>7 strides tokens by 2. Warp-uniform
// predicated loads (@!P issues no transaction), 8-wide front-batched.
// Accumulator flushes via atomicAdd only at group boundaries.
__device__ __forceinline__ void flush_acc(int b, int g, int lane, float4 a) {
    float* dst = &d_sums[((size_t)b*GG + g)*DD + lane*4];
    atomicAdd(dst+0, a.x); atomicAdd(dst+1, a.y);
    atomicAdd(dst+2, a.z); atomicAdd(dst+3, a.w);
}

__global__ void __launch_bounds__(256) k_main(const float* __restrict__ batch,
                                              const int* __restrict__ pad) {
    __shared__ int s_tok[CHUNK];
    __shared__ int s_grp[CHUNK];
    __shared__ int s_val[CHUNK];

    int b   = blockIdx.y;
    int c0  = blockIdx.x * CHUNK;
    int tid = threadIdx.x;

    if (tid < CHUNK) {
        int t = d_st[c0 + tid];
        s_tok[tid] = t;
        s_grp[tid] = d_sg[c0 + tid];
        s_val[tid] = pad[(size_t)b*TT + t] ? 0 : 1;   // bool -> int32 transport
    }
    __syncthreads();

    // per-(b,g) valid counts: 64 threads, 16 smem reads each
    if (tid < 64) {
        int g = tid >> 3, j = tid & 7;
        int c = 0;
        #pragma unroll
        for (int k = 0; k < 16; k++) {
            int i = j*16 + k;
            c += (s_grp[i] == g) & s_val[i];
        }
        if (c) atomicAdd(&d_counts[b*GG + g], c);
    }

    int lane = tid & 127;
    int half = tid >> 7;
    const float4* bb = (const float4*)(batch + (size_t)b * TT * DD);

    float4 acc = make_float4(0.f,0.f,0.f,0.f);
    int curg = s_grp[0];

    #define PLOAD(V, J)                                                     \
        float4 V = make_float4(0.f,0.f,0.f,0.f);                            \
        if (s_val[i + 2*(J)])                                               \
            V = __ldcs(&bb[(size_t)s_tok[i + 2*(J)] * (DD/4) + lane]);

    #define ACCSTEP(J, V)                                                   \
        { int g_ = s_grp[i + 2*(J)];                                        \
          if (g_ != curg) {                                                 \
              flush_acc(b, curg, lane, acc);                                \
              acc = make_float4(0.f,0.f,0.f,0.f); curg = g_; }              \
          acc.x += (V).x; acc.y += (V).y; acc.z += (V).z; acc.w += (V).w; }

    #pragma unroll
    for (int s = 0; s < 8; s++) {
        int i = half + s*16;
        PLOAD(v0, 0) PLOAD(v1, 1) PLOAD(v2, 2) PLOAD(v3, 3)
        PLOAD(v4, 4) PLOAD(v5, 5) PLOAD(v6, 6) PLOAD(v7, 7)
        ACCSTEP(0, v0); ACCSTEP(1, v1); ACCSTEP(2, v2); ACCSTEP(3, v3);
        ACCSTEP(4, v4); ACCSTEP(5, v5); ACCSTEP(6, v6); ACCSTEP(7, v7);
    }
    flush_acc(b, curg, lane, acc);
    #undef PLOAD
    #undef ACCSTEP
}

// ------------------------------------------------------ means -> GEMM + bias
// grid (8 g, 16 o-blocks of 32, 2 b-slabs of 16) = 256 CTAs (single wave at
// 2 CTA/SM), 256 threads, 96 KB dynamic smem. Thread = 2 b-rows x 1 output,
// bq = tid>>5 -> warp-uniform b-rows so mean reads are true broadcasts.
// Inner loop steps k by 4: 2 broadcast LDS.128 (means) + 4 conflict-free
// LDS.32 (w) per warp = 6 crossbar cyc per 16 FFMA-instr -> FFMA-bound.
#define GBH2 16
#define GO2  32
#define GEMM_SMEM ((DD*GO2 + GBH2*DD) * 4)   // 98304 B

__global__ void __launch_bounds__(256) k_gemm(const float* __restrict__ W,
                                              const float* __restrict__ bias,
                                              float* __restrict__ out) {
    extern __shared__ float sm[];
    float* s_w    = sm;              // [512][32]
    float* s_mean = sm + DD*GO2;     // [16][512]

    int g   = blockIdx.x;
    int o0  = blockIdx.y * GO2;
    int b0  = blockIdx.z * GBH2;
    int tid = threadIdx.x;

    // W block: 512 rows x 32 cols -> 4096 float4, 16 per thread, coalesced
    const float4* wg = (const float4*)(W + (size_t)g*DD*OO);
    #pragma unroll
    for (int i = 0; i < 16; i++) {
        int idx = tid + i*256;         // 0..4095
        int k   = idx >> 3;
        int c4  = idx & 7;
        ((float4*)s_w)[idx] = wg[(size_t)k*(OO/4) + (o0>>2) + c4];
    }
    // means: 16 x 512 floats, divide-by-count on load
    for (int idx = tid; idx < GBH2*DD; idx += 256) {
        int bl = idx >> 9;
        int d  = idx & (DD-1);
        int bg = (b0 + bl)*GG + g;
        int c  = d_counts[bg];
        float s = d_sums[(size_t)bg*DD + d];
        s_mean[bl*DD + d] = (c > 0) ? s / (float)c : 0.0f;
    }
    __syncthreads();

    int o  = tid & 31;          // warp = 32 consecutive o -> conflict-free LDS
    int bq = tid >> 5;          // warp-uniform: 8 warps -> 16 b-rows (2 each)
    const float4* m0 = (const float4*)(s_mean + (bq*2 + 0)*DD);
    const float4* m1 = (const float4*)(s_mean + (bq*2 + 1)*DD);
    float a0 = 0.f, a1 = 0.f;

    #pragma unroll 4
    for (int k4 = 0; k4 < DD/4; k4++) {
        float4 ma = m0[k4];                 // broadcast LDS.128
        float4 mb = m1[k4];                 // broadcast LDS.128
        int kb = k4*4;
        float w0 = s_w[(kb+0)*GO2 + o];
        float w1 = s_w[(kb+1)*GO2 + o];
        float w2 = s_w[(kb+2)*GO2 + o];
        float w3 = s_w[(kb+3)*GO2 + o];
        a0 = fmaf(ma.x, w0, a0); a1 = fmaf(mb.x, w0, a1);
        a0 = fmaf(ma.y, w1, a0); a1 = fmaf(mb.y, w1, a1);
        a0 = fmaf(ma.z, w2, a0); a1 = fmaf(mb.z, w2, a1);
        a0 = fmaf(ma.w, w3, a0); a1 = fmaf(mb.w, w3, a1);
    }

    float bv = bias[(size_t)g*OO + o0 + o];
    int ba = b0 + bq*2, bc = ba + 1;
    out[((size_t)ba*GG + g)*OO + o0 + o] = a0 + bv;
    out[((size_t)bc*GG + g)*OO + o0 + o] = a1 + bv;
}

// ---------------------------------------------------------------- launcher
// metadata order: batch(f32), W(f32), b_bias(f32), token_types(i32),
//                 key_padding_mask(bool -> int32)
extern "C" void kernel_launch(void* const* d_in, const int* in_sizes, int n_in,
                              void* d_out, int out_size) {
    const float* batch = (const float*)d_in[0];
    const float* W     = (const float*)d_in[1];
    const float* bias  = (const float*)d_in[2];
    const int*   tt    = (const int*)d_in[3];
    const int*   pad   = (const int*)d_in[4];
    float* out = (float*)d_out;

    static int smem_set = 0;
    if (!smem_set) {
        cudaFuncSetAttribute(k_gemm, cudaFuncAttributeMaxDynamicSharedMemorySize,
                             GEMM_SMEM);
        smem_set = 1;
    }

    k_zero<<<BB*GG*DD/(256*4), 256>>>();
    k_sort<<<1, 256>>>(tt);

    dim3 gmain(NCHUNK, BB);
    k_main<<<gmain, 256>>>(batch, pad);

    dim3 ggemm(GG, OO/GO2, BB/GBH2);
    k_gemm<<<ggemm, 256, GEMM_SMEM>>>(W, bias, out);
}

// round 10
// speedup vs baseline: 1.3601x; 1.2191x over previous
#include <cuda_runtime.h>

#define BB   32
#define TT   4096
#define DD   512
#define GG   8
#define OO   512
#define CHUNK 128
#define NCHUNK (TT/CHUNK)   // 32

// Scratch (__device__ globals; no allocations allowed)
__device__ float d_sums[BB*GG*DD];
__device__ int   d_counts[BB*GG];
__device__ int   d_st[TT];      // token ids, group-sorted (shared across b)
__device__ int   d_sg[TT];      // group id per sorted slot

// ---------------------------------------------------------------- zero
__global__ void __launch_bounds__(256) k_zero() {
    int i = blockIdx.x * 256 + threadIdx.x;
    ((float4*)d_sums)[i] = make_float4(0.f,0.f,0.f,0.f);
    if (blockIdx.x == 0 && threadIdx.x < BB*GG) d_counts[threadIdx.x] = 0;
}

// ---------------------------------------------------------------- sort
// 1 CTA, 8 warps. Warp g scans all TT token types (16 KB, L1-resident after
// first pass) and ballot-compacts its group's token ids. No atomics.
__global__ void __launch_bounds__(256) k_sort(const int* __restrict__ tt) {
    __shared__ int s_cnt[GG];
    int tid  = threadIdx.x;
    int lane = tid & 31;
    int w    = tid >> 5;          // warp == group

    int c = 0;
    #pragma unroll 4
    for (int t0 = 0; t0 < TT; t0 += 32)
        c += (tt[t0 + lane] == w);
    #pragma unroll
    for (int off = 16; off > 0; off >>= 1)
        c += __shfl_down_sync(0xffffffffu, c, off);
    if (lane == 0) s_cnt[w] = c;
    __syncthreads();

    int base = 0;
    #pragma unroll
    for (int g = 0; g < GG; g++) base += (g < w) ? s_cnt[g] : 0;

    int pos = base;
    for (int t0 = 0; t0 < TT; t0 += 32) {
        int g = tt[t0 + lane];
        unsigned m = __ballot_sync(0xffffffffu, g == w);
        if (g == w) {
            int r = __popc(m & ((1u << lane) - 1u));
            d_st[pos + r] = t0 + lane;
            d_sg[pos + r] = w;
        }
        pos += __popc(m);
    }
}

// ------------------------------------------------------------- masked sums
// grid (NCHUNK, BB), 256 threads (R4-measured-best variant). Warp-uniform
// predicated loads, 8-wide front-batched; atomic flush at group boundaries.
__device__ __forceinline__ void flush_acc(int b, int g, int lane, float4 a) {
    float* dst = &d_sums[((size_t)b*GG + g)*DD + lane*4];
    atomicAdd(dst+0, a.x); atomicAdd(dst+1, a.y);
    atomicAdd(dst+2, a.z); atomicAdd(dst+3, a.w);
}

__global__ void __launch_bounds__(256) k_main(const float* __restrict__ batch,
                                              const int* __restrict__ pad) {
    __shared__ int s_tok[CHUNK];
    __shared__ int s_grp[CHUNK];
    __shared__ int s_val[CHUNK];

    int b   = blockIdx.y;
    int c0  = blockIdx.x * CHUNK;
    int tid = threadIdx.x;

    if (tid < CHUNK) {
        int t = d_st[c0 + tid];
        s_tok[tid] = t;
        s_grp[tid] = d_sg[c0 + tid];
        s_val[tid] = pad[(size_t)b*TT + t] ? 0 : 1;   // bool -> int32 transport
    }
    __syncthreads();

    // per-(b,g) valid counts: 64 threads, 16 smem reads each
    if (tid < 64) {
        int g = tid >> 3, j = tid & 7;
        int c = 0;
        #pragma unroll
        for (int k = 0; k < 16; k++) {
            int i = j*16 + k;
            c += (s_grp[i] == g) & s_val[i];
        }
        if (c) atomicAdd(&d_counts[b*GG + g], c);
    }

    int lane = tid & 127;
    int half = tid >> 7;
    const float4* bb = (const float4*)(batch + (size_t)b * TT * DD);

    float4 acc = make_float4(0.f,0.f,0.f,0.f);
    int curg = s_grp[0];

    #define PLOAD(V, J)                                                     \
        float4 V = make_float4(0.f,0.f,0.f,0.f);                            \
        if (s_val[i + 2*(J)])                                               \
            V = __ldcs(&bb[(size_t)s_tok[i + 2*(J)] * (DD/4) + lane]);

    #define ACCSTEP(J, V)                                                   \
        { int g_ = s_grp[i + 2*(J)];                                        \
          if (g_ != curg) {                                                 \
              flush_acc(b, curg, lane, acc);                                \
              acc = make_float4(0.f,0.f,0.f,0.f); curg = g_; }              \
          acc.x += (V).x; acc.y += (V).y; acc.z += (V).z; acc.w += (V).w; }

    #pragma unroll
    for (int s = 0; s < 8; s++) {
        int i = half + s*16;
        PLOAD(v0, 0) PLOAD(v1, 1) PLOAD(v2, 2) PLOAD(v3, 3)
        PLOAD(v4, 4) PLOAD(v5, 5) PLOAD(v6, 6) PLOAD(v7, 7)
        ACCSTEP(0, v0); ACCSTEP(1, v1); ACCSTEP(2, v2); ACCSTEP(3, v3);
        ACCSTEP(4, v4); ACCSTEP(5, v5); ACCSTEP(6, v6); ACCSTEP(7, v7);
    }
    flush_acc(b, curg, lane, acc);
    #undef PLOAD
    #undef ACCSTEP
}

// ------------------------------------------------------ means -> GEMM + bias
// grid (8 g, 16 o-blocks of 32) = 128 CTAs, 512 threads.
// warp = one d-slice of 32 (d warp-uniform), lanes = 32 consecutive o.
// Phase 1: transpose-divide means into smem [d][b] (pad 36).
// Phase 2: front-batch 32 W loads into registers (coalesced, MLP 32), then
//          1024 FFMAs vs broadcast LDS.128 mean reads -> FFMA-bound.
// Phase 3: slice reduction via padded smem, coalesced STG + bias.
#define GOB  32              // o per CTA
#define NSL  16              // d-slices (= warps)
#define SLD  (DD/NSL)        // 32 d per slice
#define MTP  36              // padded b-row (16B-aligned, conflict-spread)
#define GEMM_SMEM ((DD*MTP + NSL*GOB*MTP) * 4)   // 73728*2 = 147456 B

__global__ void __launch_bounds__(512) k_gemm(const float* __restrict__ W,
                                              const float* __restrict__ bias,
                                              float* __restrict__ out) {
    extern __shared__ float sm[];
    float* s_mt  = sm;               // [512][36]  means^T: [d][b]
    float* s_red = sm + DD*MTP;      // [16][32][36] slice partials

    __shared__ float s_inv[BB];

    int g   = blockIdx.x;
    int o0  = blockIdx.y * GOB;
    int tid = threadIdx.x;

    if (tid < BB) {
        int c = d_counts[tid*GG + g];
        s_inv[tid] = (c > 0) ? 1.0f / (float)c : 0.0f;
    }
    __syncthreads();

    // transpose-divide: 32b x 512d, coalesced loads, 4-way-conflict stores
    for (int idx = tid; idx < BB*DD; idx += 512) {
        int b = idx >> 9;
        int d = idx & (DD-1);
        float s = d_sums[((size_t)b*GG + g)*DD + d];
        s_mt[d*MTP + b] = s * s_inv[b];
    }
    __syncthreads();

    int o  = tid & 31;          // lane -> output column
    int sl = tid >> 5;          // warp -> d-slice
    int d0 = sl * SLD;

    // front-batched W strip: 32 coalesced LDG.32, one DRAM round-trip
    const float* wp = W + ((size_t)g*DD + d0)*OO + o0 + o;
    float wreg[SLD];
    #pragma unroll
    for (int k = 0; k < SLD; k++)
        wreg[k] = __ldg(wp + (size_t)k*OO);

    float acc[BB];
    #pragma unroll
    for (int b = 0; b < BB; b++) acc[b] = 0.f;

    #pragma unroll
    for (int k = 0; k < SLD; k++) {
        const float4* mrow = (const float4*)(s_mt + (d0 + k)*MTP);
        float w = wreg[k];
        #pragma unroll
        for (int j = 0; j < 8; j++) {
            float4 m = mrow[j];                    // broadcast LDS.128
            acc[j*4+0] = fmaf(m.x, w, acc[j*4+0]);
            acc[j*4+1] = fmaf(m.y, w, acc[j*4+1]);
            acc[j*4+2] = fmaf(m.z, w, acc[j*4+2]);
            acc[j*4+3] = fmaf(m.w, w, acc[j*4+3]);
        }
    }

    // stash slice partials: [sl][o][b], padded row
    float* rp = s_red + (sl*GOB + o)*MTP;
    #pragma unroll
    for (int j = 0; j < 8; j++)
        ((float4*)rp)[j] = make_float4(acc[j*4], acc[j*4+1],
                                       acc[j*4+2], acc[j*4+3]);
    __syncthreads();

    // reduce 16 slices; consecutive threads = consecutive o -> coalesced STG
    for (int idx = tid; idx < GOB*BB; idx += 512) {
        int oo = idx & 31;
        int b  = idx >> 5;
        float s = 0.f;
        #pragma unroll
        for (int sl2 = 0; sl2 < NSL; sl2++)
            s += s_red[(sl2*GOB + oo)*MTP + b];
        out[((size_t)b*GG + g)*OO + o0 + oo] =
            s + bias[(size_t)g*OO + o0 + oo];
    }
}

// ---------------------------------------------------------------- launcher
// metadata order: batch(f32), W(f32), b_bias(f32), token_types(i32),
//                 key_padding_mask(bool -> int32)
extern "C" void kernel_launch(void* const* d_in, const int* in_sizes, int n_in,
                              void* d_out, int out_size) {
    const float* batch = (const float*)d_in[0];
    const float* W     = (const float*)d_in[1];
    const float* bias  = (const float*)d_in[2];
    const int*   tt    = (const int*)d_in[3];
    const int*   pad   = (const int*)d_in[4];
    float* out = (float*)d_out;

    cudaFuncSetAttribute(k_gemm, cudaFuncAttributeMaxDynamicSharedMemorySize,
                         GEMM_SMEM);

    k_zero<<<BB*GG*DD/(256*4), 256>>>();
    k_sort<<<1, 256>>>(tt);

    dim3 gmain(NCHUNK, BB);
    k_main<<<gmain, 256>>>(batch, pad);

    dim3 ggemm(GG, OO/GOB);
    k_gemm<<<ggemm, 512, GEMM_SMEM>>>(W, bias, out);
}